// round 2
// baseline (speedup 1.0000x reference)
#include <cuda_runtime.h>
#include <math.h>

// Problem constants (fixed by the reference)
#define T_TOK   4096
#define D_MODEL 512
#define D_FF    2048
#define N_EXP   8
#define K_ACT   2
#define NPAIR   (T_TOK * K_ACT)   // 8192 (token, slot) pairs

// GEMM tiling
#define BM 128
#define BN 128
#define BK 8
#define MAX_TILES (NPAIR / BM + N_EXP)   // 64 + 8 = 72 worst case

// ---------------- device scratch (no allocations allowed) ----------------
__device__ int   g_is32;                  // 1 if selected_experts arrived as int32
__device__ int   g_counts[N_EXP];
__device__ int   g_fill[N_EXP];
__device__ int   g_offsets[N_EXP + 1];
__device__ int   g_pairs[NPAIR];          // pair ids sorted by expert
__device__ int   g_tileExpert[MAX_TILES];
__device__ int   g_tileRow[MAX_TILES];    // start index into g_pairs
__device__ int   g_tileRows[MAX_TILES];   // rows in this tile (<= BM)
__device__ int   g_numTiles;
__device__ float g_H[(size_t)NPAIR * D_FF];  // 64 MB intermediate (gelu(x@W1))

// expert id for pair p, robust to int32-vs-int64 storage
__device__ __forceinline__ int pair_expert(const int* sel32, int p) {
    int e = g_is32 ? sel32[p] : sel32[2 * p];  // int64 LE: low word at 2p
    // clamp: never trap on unexpected data (wrong answer is visible, a trap is not)
    return min(max(e, 0), N_EXP - 1);
}

// ---------------- routing ----------------
__global__ void k_init(const int* __restrict__ sel32) {
    int i = blockIdx.x * blockDim.x + threadIdx.x;
    if (i < N_EXP && blockIdx.x == 0) { g_counts[i] = 0; g_fill[i] = 0; }
    if (i == 0) g_is32 = 0;
}

// If ANY odd int32 word is nonzero, the buffer is genuine int32 data.
// (int64 values 0..7 have zero high words at every odd index.)
__global__ void k_detect(const int* __restrict__ sel32) {
    int i = blockIdx.x * blockDim.x + threadIdx.x;  // 0..4095
    if (i < NPAIR / 2 && sel32[2 * i + 1] != 0) g_is32 = 1;
}

__global__ void k_hist(const int* __restrict__ sel32) {
    int p = blockIdx.x * blockDim.x + threadIdx.x;
    if (p < NPAIR) atomicAdd(&g_counts[pair_expert(sel32, p)], 1);
}

__global__ void k_scan(float* __restrict__ out) {
    // single thread: 8 experts, trivial
    int off = 0, nt = 0;
    for (int e = 0; e < N_EXP; e++) {
        g_offsets[e] = off;
        int c = g_counts[e];
        out[(size_t)NPAIR * D_MODEL + e] = (float)c / (float)T_TOK;  // expert_loads
        for (int r0 = 0; r0 < c; r0 += BM) {
            g_tileExpert[nt] = e;
            g_tileRow[nt]    = off + r0;
            g_tileRows[nt]   = min(BM, c - r0);
            nt++;
        }
        off += c;
    }
    g_offsets[N_EXP] = off;
    g_numTiles = nt;
}

__global__ void k_scatter(const int* __restrict__ sel32) {
    int p = blockIdx.x * blockDim.x + threadIdx.x;
    if (p < NPAIR) {
        int e = pair_expert(sel32, p);
        int pos = g_offsets[e] + atomicAdd(&g_fill[e], 1);
        g_pairs[pos] = p;
    }
}

// ---------------- GELU (exact, erf-based, matches approximate=False) ----------------
__device__ __forceinline__ float gelu_exact(float v) {
    return 0.5f * v * (1.0f + erff(v * 0.70710678118654752f));
}

// ---------------- GEMM1: H = gelu(X_gathered @ W1[e]) ----------------
// grid: (MAX_TILES, D_FF/BN), block: 256
__global__ __launch_bounds__(256) void k_gemm1(const float* __restrict__ X,
                                               const float* __restrict__ W1) {
    int tile = blockIdx.x;
    if (tile >= g_numTiles) return;
    int e    = g_tileExpert[tile];
    int row0 = g_tileRow[tile];
    int rows = g_tileRows[tile];
    int n0   = blockIdx.y * BN;

    const float* B = W1 + (size_t)e * D_MODEL * D_FF;

    __shared__ __align__(16) float As[BK][BM];
    __shared__ __align__(16) float Bs[BK][BN];

    int tid = threadIdx.x;
    // A-tile loading: 128 rows x 8 k, one float4 per thread
    int lr = tid >> 1;
    int lk = (tid & 1) << 2;
    int arow  = (lr < rows) ? lr : (rows - 1);   // clamp padded rows (rows >= 1)
    int token = g_pairs[row0 + arow] >> 1;       // pair = t*2 + slot
    const float* Arow = X + (size_t)token * D_MODEL + lk;

    // B-tile loading: 8 k x 128 n, one float4 per thread
    int bk = tid >> 5;
    int bn = (tid & 31) << 2;
    const float* Bld = B + (size_t)bk * D_FF + n0 + bn;

    int tr = tid >> 4;   // 0..15
    int tc = tid & 15;   // 0..15

    float acc[8][8];
#pragma unroll
    for (int i = 0; i < 8; i++)
#pragma unroll
        for (int j = 0; j < 8; j++) acc[i][j] = 0.0f;

    for (int k0 = 0; k0 < D_MODEL; k0 += BK) {
        float4 a = *(const float4*)(Arow + k0);
        As[lk + 0][lr] = a.x; As[lk + 1][lr] = a.y;
        As[lk + 2][lr] = a.z; As[lk + 3][lr] = a.w;
        float4 b = *(const float4*)(Bld + (size_t)k0 * D_FF);
        *(float4*)(&Bs[bk][bn]) = b;
        __syncthreads();
#pragma unroll
        for (int k = 0; k < BK; k++) {
            float ra[8], rb[8];
            *(float4*)(ra)     = *(const float4*)(&As[k][tr * 8]);
            *(float4*)(ra + 4) = *(const float4*)(&As[k][tr * 8 + 4]);
            *(float4*)(rb)     = *(const float4*)(&Bs[k][tc * 8]);
            *(float4*)(rb + 4) = *(const float4*)(&Bs[k][tc * 8 + 4]);
#pragma unroll
            for (int i = 0; i < 8; i++)
#pragma unroll
                for (int j = 0; j < 8; j++)
                    acc[i][j] = fmaf(ra[i], rb[j], acc[i][j]);
        }
        __syncthreads();
    }

#pragma unroll
    for (int i = 0; i < 8; i++) {
        int m = tr * 8 + i;
        if (m < rows) {
            float* Hp = g_H + (size_t)(row0 + m) * D_FF + n0 + tc * 8;
            float4 v0, v1;
            v0.x = gelu_exact(acc[i][0]); v0.y = gelu_exact(acc[i][1]);
            v0.z = gelu_exact(acc[i][2]); v0.w = gelu_exact(acc[i][3]);
            v1.x = gelu_exact(acc[i][4]); v1.y = gelu_exact(acc[i][5]);
            v1.z = gelu_exact(acc[i][6]); v1.w = gelu_exact(acc[i][7]);
            *(float4*)(Hp)     = v0;
            *(float4*)(Hp + 4) = v1;
        }
    }
}

// ---------------- GEMM2: out[pair] = H @ W2[e] ----------------
// grid: (MAX_TILES, D_MODEL/BN), block: 256
__global__ __launch_bounds__(256) void k_gemm2(const float* __restrict__ W2,
                                               float* __restrict__ out) {
    int tile = blockIdx.x;
    if (tile >= g_numTiles) return;
    int e    = g_tileExpert[tile];
    int row0 = g_tileRow[tile];
    int rows = g_tileRows[tile];
    int n0   = blockIdx.y * BN;

    const float* B = W2 + (size_t)e * D_FF * D_MODEL;

    __shared__ __align__(16) float As[BK][BM];
    __shared__ __align__(16) float Bs[BK][BN];

    int tid = threadIdx.x;
    int lr = tid >> 1;
    int lk = (tid & 1) << 2;
    int arow = (lr < rows) ? lr : (rows - 1);
    const float* Arow = g_H + (size_t)(row0 + arow) * D_FF + lk;

    int bk = tid >> 5;
    int bn = (tid & 31) << 2;
    const float* Bld = B + (size_t)bk * D_MODEL + n0 + bn;

    int tr = tid >> 4;
    int tc = tid & 15;

    float acc[8][8];
#pragma unroll
    for (int i = 0; i < 8; i++)
#pragma unroll
        for (int j = 0; j < 8; j++) acc[i][j] = 0.0f;

    for (int k0 = 0; k0 < D_FF; k0 += BK) {
        float4 a = *(const float4*)(Arow + k0);
        As[lk + 0][lr] = a.x; As[lk + 1][lr] = a.y;
        As[lk + 2][lr] = a.z; As[lk + 3][lr] = a.w;
        float4 b = *(const float4*)(Bld + (size_t)k0 * D_MODEL);
        *(float4*)(&Bs[bk][bn]) = b;
        __syncthreads();
#pragma unroll
        for (int k = 0; k < BK; k++) {
            float ra[8], rb[8];
            *(float4*)(ra)     = *(const float4*)(&As[k][tr * 8]);
            *(float4*)(ra + 4) = *(const float4*)(&As[k][tr * 8 + 4]);
            *(float4*)(rb)     = *(const float4*)(&Bs[k][tc * 8]);
            *(float4*)(rb + 4) = *(const float4*)(&Bs[k][tc * 8 + 4]);
#pragma unroll
            for (int i = 0; i < 8; i++)
#pragma unroll
                for (int j = 0; j < 8; j++)
                    acc[i][j] = fmaf(ra[i], rb[j], acc[i][j]);
        }
        __syncthreads();
    }

#pragma unroll
    for (int i = 0; i < 8; i++) {
        int m = tr * 8 + i;
        if (m < rows) {
            int pair = g_pairs[row0 + m];
            float* Op = out + (size_t)pair * D_MODEL + n0 + tc * 8;
            float4 v0, v1;
            v0.x = acc[i][0]; v0.y = acc[i][1]; v0.z = acc[i][2]; v0.w = acc[i][3];
            v1.x = acc[i][4]; v1.y = acc[i][5]; v1.z = acc[i][6]; v1.w = acc[i][7];
            *(float4*)(Op)     = v0;
            *(float4*)(Op + 4) = v1;
        }
    }
}

// ---------------- launch ----------------
extern "C" void kernel_launch(void* const* d_in, const int* in_sizes, int n_in,
                              void* d_out, int out_size) {
    const float* X     = (const float*)d_in[0];  // [T, D_MODEL]
    const int*   sel32 = (const int*)d_in[1];    // [T, K] int32 or int64 (detected)
    // d_in[2] expert_masks — unused by the reference
    const float* W1    = (const float*)d_in[3];  // [E, D, F]
    const float* W2    = (const float*)d_in[4];  // [E, F, D]
    float*       out   = (float*)d_out;          // [T*K*D] outputs ++ [E] loads

    k_init<<<1, 32>>>(sel32);
    k_detect<<<(NPAIR / 2 + 255) / 256, 256>>>(sel32);
    k_hist<<<NPAIR / 256, 256>>>(sel32);
    k_scan<<<1, 1>>>(out);
    k_scatter<<<NPAIR / 256, 256>>>(sel32);

    dim3 grid1(MAX_TILES, D_FF / BN);     // 72 x 16
    k_gemm1<<<grid1, 256>>>(X, W1);

    dim3 grid2(MAX_TILES, D_MODEL / BN);  // 72 x 4
    k_gemm2<<<grid2, 256>>>(W2, out);
}

// round 4
// speedup vs baseline: 1.7675x; 1.7675x over previous
#include <cuda_runtime.h>
#include <cuda_bf16.h>
#include <math.h>
#include <stdint.h>

// Problem constants
#define T_TOK   4096
#define D_MODEL 512
#define D_FF    2048
#define N_EXP   8
#define K_ACT   2
#define NPAIR   (T_TOK * K_ACT)          // 8192
#define BM      128
#define MAX_TILES (NPAIR / BM + N_EXP)   // 72

// ---------------- device scratch ----------------
__device__ int g_is32;
__device__ int g_counts[N_EXP];
__device__ int g_fill[N_EXP];
__device__ int g_offsets[N_EXP + 1];
__device__ int g_pairs[NPAIR];
__device__ int g_tileExpert[MAX_TILES];
__device__ int g_tileRow[MAX_TILES];
__device__ int g_tileRows[MAX_TILES];
__device__ int g_numTiles;

__device__ __align__(16) __nv_bfloat16 g_Xhi[(size_t)T_TOK * D_MODEL];
__device__ __align__(16) __nv_bfloat16 g_Xlo[(size_t)T_TOK * D_MODEL];
__device__ __align__(16) __nv_bfloat16 g_W1thi[(size_t)N_EXP * D_FF * D_MODEL]; // [e][n][k]
__device__ __align__(16) __nv_bfloat16 g_W1tlo[(size_t)N_EXP * D_FF * D_MODEL];
__device__ __align__(16) __nv_bfloat16 g_W2thi[(size_t)N_EXP * D_MODEL * D_FF]; // [e][d][f]
__device__ __align__(16) __nv_bfloat16 g_W2tlo[(size_t)N_EXP * D_MODEL * D_FF];
__device__ __align__(16) __nv_bfloat16 g_Hhi[(size_t)NPAIR * D_FF];
__device__ __align__(16) __nv_bfloat16 g_Hlo[(size_t)NPAIR * D_FF];

// ---------------- PTX helpers (all baseline sm_80+, compile under compute_103) ----
__device__ __forceinline__ uint32_t smem_u32(const void* p) {
    uint32_t a;
    asm("{ .reg .u64 t; cvta.to.shared.u64 t, %1; cvt.u32.u64 %0, t; }" : "=r"(a) : "l"(p));
    return a;
}
#define CP16(dst, src)  asm volatile("cp.async.cg.shared.global [%0], [%1], 16;" :: "r"(dst), "l"(src))
#define CP_COMMIT()     asm volatile("cp.async.commit_group;" ::: "memory")
#define CP_WAIT(n)      asm volatile("cp.async.wait_group %0;" :: "n"(n) : "memory")

__device__ __forceinline__ void ldsm_x4(uint32_t* r, uint32_t addr) {
    asm volatile("ldmatrix.sync.aligned.m8n8.x4.shared.b16 {%0,%1,%2,%3}, [%4];"
        : "=r"(r[0]), "=r"(r[1]), "=r"(r[2]), "=r"(r[3]) : "r"(addr));
}
__device__ __forceinline__ void mma16816(float* c, const uint32_t* a, uint32_t b0, uint32_t b1) {
    asm volatile("mma.sync.aligned.m16n8k16.row.col.f32.bf16.bf16.f32 "
        "{%0,%1,%2,%3}, {%4,%5,%6,%7}, {%8,%9}, {%0,%1,%2,%3};"
        : "+f"(c[0]), "+f"(c[1]), "+f"(c[2]), "+f"(c[3])
        : "r"(a[0]), "r"(a[1]), "r"(a[2]), "r"(a[3]), "r"(b0), "r"(b1));
}

// ---------------- routing (unchanged from passing R2) ----------------
__device__ __forceinline__ int pair_expert(const int* sel32, int p) {
    int e = g_is32 ? sel32[p] : sel32[2 * p];
    return min(max(e, 0), N_EXP - 1);
}
__global__ void k_init(const int* __restrict__ sel32) {
    int i = blockIdx.x * blockDim.x + threadIdx.x;
    if (i < N_EXP) { g_counts[i] = 0; g_fill[i] = 0; }
    if (i == 0) g_is32 = 0;
}
__global__ void k_detect(const int* __restrict__ sel32) {
    int i = blockIdx.x * blockDim.x + threadIdx.x;
    if (i < NPAIR / 2 && sel32[2 * i + 1] != 0) g_is32 = 1;
}
__global__ void k_hist(const int* __restrict__ sel32) {
    int p = blockIdx.x * blockDim.x + threadIdx.x;
    if (p < NPAIR) atomicAdd(&g_counts[pair_expert(sel32, p)], 1);
}
__global__ void k_scan(float* __restrict__ out) {
    int off = 0, nt = 0;
    for (int e = 0; e < N_EXP; e++) {
        g_offsets[e] = off;
        int c = g_counts[e];
        out[(size_t)NPAIR * D_MODEL + e] = (float)c / (float)T_TOK;
        for (int r0 = 0; r0 < c; r0 += BM) {
            g_tileExpert[nt] = e; g_tileRow[nt] = off + r0;
            g_tileRows[nt] = min(BM, c - r0); nt++;
        }
        off += c;
    }
    g_offsets[N_EXP] = off;
    g_numTiles = nt;
}
__global__ void k_scatter(const int* __restrict__ sel32) {
    int p = blockIdx.x * blockDim.x + threadIdx.x;
    if (p < NPAIR) {
        int e = pair_expert(sel32, p);
        g_pairs[g_offsets[e] + atomicAdd(&g_fill[e], 1)] = p;
    }
}

// ---------------- bf16 split conversions ----------------
__global__ void k_convX(const float* __restrict__ X) {
    int i = (blockIdx.x * 256 + threadIdx.x) * 4;
    float4 v = *(const float4*)(X + i);
    float f[4] = {v.x, v.y, v.z, v.w};
    __nv_bfloat16 h[4], l[4];
#pragma unroll
    for (int j = 0; j < 4; j++) {
        h[j] = __float2bfloat16(f[j]);
        l[j] = __float2bfloat16(f[j] - __bfloat162float(h[j]));
    }
    *(uint2*)(g_Xhi + i) = *(uint2*)h;
    *(uint2*)(g_Xlo + i) = *(uint2*)l;
}

// transpose [R,C] fp32 -> [C,R] bf16 hi/lo, per expert (blockIdx.z)
__global__ void k_convWt(const float* __restrict__ Win, int isW2) {
    const int R = isW2 ? D_FF : D_MODEL;
    const int C = isW2 ? D_MODEL : D_FF;
    int e = blockIdx.z;
    const float* in = Win + (size_t)e * R * C;
    __nv_bfloat16* oh = (isW2 ? g_W2thi : g_W1thi) + (size_t)e * R * C;
    __nv_bfloat16* ol = (isW2 ? g_W2tlo : g_W1tlo) + (size_t)e * R * C;
    __shared__ float tile[32][33];
    int c0 = blockIdx.x * 32, r0 = blockIdx.y * 32;
    int tx = threadIdx.x, ty = threadIdx.y; // (32, 8)
#pragma unroll
    for (int j = 0; j < 4; j++)
        tile[ty * 4 + j][tx] = in[(size_t)(r0 + ty * 4 + j) * C + c0 + tx];
    __syncthreads();
#pragma unroll
    for (int j = 0; j < 4; j++) {
        float v = tile[tx][ty * 4 + j];
        __nv_bfloat16 h = __float2bfloat16(v);
        size_t o = (size_t)(c0 + ty * 4 + j) * R + r0 + tx;
        oh[o] = h;
        ol[o] = __float2bfloat16(v - __bfloat162float(h));
    }
}

__device__ __forceinline__ float gelu_exact(float v) {
    return 0.5f * v * (1.0f + erff(v * 0.70710678118654752f));
}

// ---------------- split-bf16 GEMM via mma.sync (HMMA) ----------------
// CTA tile 128x128, BK=32, 3-stage cp.async pipeline, 8 warps (4M x 2N).
// Stage layout (padded rows, 80B): Ahi | Alo | Bhi | Blo, each 128x40 bf16.
#define ROWB   80
#define ARR_SZ (128 * ROWB)        // 10240 B
#define STG_SZ (4 * ARR_SZ)        // 40960 B
#define NSTG   3
#define SMEM_GEMM (NSTG * STG_SZ)  // 122880 B

template<bool G1>
__global__ __launch_bounds__(256, 1) void k_mma(float* __restrict__ out) {
    constexpr int KDIM = G1 ? D_MODEL : D_FF;
    constexpr int NCH  = KDIM / 32;

    int tile = blockIdx.x;
    if (tile >= g_numTiles) return;
    int e    = g_tileExpert[tile];
    int row0 = g_tileRow[tile];
    int rows = g_tileRows[tile];
    int n0   = blockIdx.y * 128;

    extern __shared__ __align__(128) char smem[];
    uint32_t sb = smem_u32(smem);
    __shared__ int s_rows[128];
    __shared__ int s_pair[128];

    int tid = threadIdx.x;
    int wid = tid >> 5, l = tid & 31;

    if (tid < 128) {
        int rr = min(tid, rows - 1);
        int p = g_pairs[row0 + rr];
        s_pair[tid] = p;
        s_rows[tid] = G1 ? (p >> 1) : (row0 + rr);
    }
    __syncthreads();

    const __nv_bfloat16* Ahi = G1 ? g_Xhi : g_Hhi;
    const __nv_bfloat16* Alo = G1 ? g_Xlo : g_Hlo;
    const size_t wstride = (size_t)D_FF * D_MODEL;
    const __nv_bfloat16* Bhi = (G1 ? g_W1thi : g_W2thi) + (size_t)e * wstride;
    const __nv_bfloat16* Blo = (G1 ? g_W1tlo : g_W2tlo) + (size_t)e * wstride;

    // per-thread load slice: row = tid/2, half = tid&1 covers 16 bf16 (32B)
    int lrow = tid >> 1, half = tid & 1;
    const __nv_bfloat16* aHp = Ahi + (size_t)s_rows[lrow] * KDIM + half * 16;
    const __nv_bfloat16* aLp = Alo + (size_t)s_rows[lrow] * KDIM + half * 16;
    const __nv_bfloat16* bHp = Bhi + (size_t)(n0 + lrow) * KDIM + half * 16;
    const __nv_bfloat16* bLp = Blo + (size_t)(n0 + lrow) * KDIM + half * 16;
    uint32_t dOff = (uint32_t)(lrow * ROWB + half * 32);

#define LOAD_STAGE(sidx, k0)                                         \
    {                                                                \
        uint32_t _st = sb + (uint32_t)(sidx) * STG_SZ + dOff;        \
        CP16(_st,                aHp + (k0));                        \
        CP16(_st + 16,           aHp + (k0) + 8);                    \
        CP16(_st + ARR_SZ,       aLp + (k0));                        \
        CP16(_st + ARR_SZ + 16,  aLp + (k0) + 8);                    \
        CP16(_st + 2*ARR_SZ,     bHp + (k0));                        \
        CP16(_st + 2*ARR_SZ+16,  bHp + (k0) + 8);                    \
        CP16(_st + 3*ARR_SZ,     bLp + (k0));                        \
        CP16(_st + 3*ARR_SZ+16,  bLp + (k0) + 8);                    \
        CP_COMMIT();                                                 \
    }

    int warp_m = (wid >> 1) * 32;
    int warp_n = (wid & 1) * 64;

    float acc[2][8][4];
#pragma unroll
    for (int i = 0; i < 2; i++)
#pragma unroll
        for (int j = 0; j < 8; j++)
#pragma unroll
            for (int q = 0; q < 4; q++) acc[i][j][q] = 0.0f;

    // ldmatrix per-lane base offsets
    uint32_t aLane = (uint32_t)((warp_m + (l & 15)) * ROWB + (l >> 4) * 16);
    uint32_t bLane = (uint32_t)(2 * ARR_SZ + (warp_n + (l & 15)) * ROWB + (l >> 4) * 16);

    // prologue: stages 0,1
    LOAD_STAGE(0, 0);
    LOAD_STAGE(1, 32);

    int s = 0;
    for (int c = 0; c < NCH; c++) {
        CP_WAIT(1);
        __syncthreads();
        if (c + 2 < NCH) {
            int sn = s + 2; if (sn >= NSTG) sn -= NSTG;
            LOAD_STAGE(sn, (c + 2) * 32);
        }
        uint32_t st = sb + (uint32_t)s * STG_SZ;
#pragma unroll
        for (int kk = 0; kk < 2; kk++) {
            uint32_t ah[2][4], al[2][4], bh[4][4], bl[4][4];
#pragma unroll
            for (int mb = 0; mb < 2; mb++) {
                ldsm_x4(ah[mb], st + aLane + (uint32_t)(mb * 16 * ROWB + kk * 32));
                ldsm_x4(al[mb], st + ARR_SZ + aLane + (uint32_t)(mb * 16 * ROWB + kk * 32));
            }
#pragma unroll
            for (int nb2 = 0; nb2 < 4; nb2++) {
                ldsm_x4(bh[nb2], st + bLane + (uint32_t)(nb2 * 16 * ROWB + kk * 32));
                ldsm_x4(bl[nb2], st + ARR_SZ + bLane + (uint32_t)(nb2 * 16 * ROWB + kk * 32));
            }
#pragma unroll
            for (int mb = 0; mb < 2; mb++)
#pragma unroll
                for (int nb = 0; nb < 8; nb++) {
                    int nb2 = nb >> 1, sel = nb & 1;
                    mma16816(acc[mb][nb], ah[mb], bh[nb2][sel], bh[nb2][sel + 2]);
                    mma16816(acc[mb][nb], ah[mb], bl[nb2][sel], bl[nb2][sel + 2]);
                    mma16816(acc[mb][nb], al[mb], bh[nb2][sel], bh[nb2][sel + 2]);
                }
        }
        __syncthreads();
        s++; if (s >= NSTG) s = 0;
    }

    // epilogue
#pragma unroll
    for (int mb = 0; mb < 2; mb++)
#pragma unroll
        for (int nb = 0; nb < 8; nb++) {
            int rbase = warp_m + mb * 16 + (l >> 2);
            int col   = warp_n + nb * 8 + (l & 3) * 2;
#pragma unroll
            for (int p = 0; p < 2; p++) {
                int m = rbase + p * 8;
                if (m < rows) {
                    float y0 = acc[mb][nb][2 * p];
                    float y1 = acc[mb][nb][2 * p + 1];
                    if (G1) {
                        y0 = gelu_exact(y0);
                        y1 = gelu_exact(y1);
                        __nv_bfloat162 hh, ll;
                        hh.x = __float2bfloat16(y0);
                        hh.y = __float2bfloat16(y1);
                        ll.x = __float2bfloat16(y0 - __bfloat162float(hh.x));
                        ll.y = __float2bfloat16(y1 - __bfloat162float(hh.y));
                        size_t o = (size_t)(row0 + m) * D_FF + n0 + col;
                        *(uint32_t*)(g_Hhi + o) = *(uint32_t*)&hh;
                        *(uint32_t*)(g_Hlo + o) = *(uint32_t*)&ll;
                    } else {
                        size_t o = (size_t)s_pair[m] * D_MODEL + n0 + col;
                        float2 v; v.x = y0; v.y = y1;
                        *(float2*)(out + o) = v;
                    }
                }
            }
        }
#undef LOAD_STAGE
}

// ---------------- launch ----------------
extern "C" void kernel_launch(void* const* d_in, const int* in_sizes, int n_in,
                              void* d_out, int out_size) {
    const float* X     = (const float*)d_in[0];
    const int*   sel32 = (const int*)d_in[1];
    const float* W1    = (const float*)d_in[3];
    const float* W2    = (const float*)d_in[4];
    float*       out   = (float*)d_out;

    cudaFuncSetAttribute((const void*)k_mma<true>,  cudaFuncAttributeMaxDynamicSharedMemorySize, SMEM_GEMM);
    cudaFuncSetAttribute((const void*)k_mma<false>, cudaFuncAttributeMaxDynamicSharedMemorySize, SMEM_GEMM);

    k_init<<<1, 32>>>(sel32);
    k_detect<<<(NPAIR / 2 + 255) / 256, 256>>>(sel32);
    k_hist<<<NPAIR / 256, 256>>>(sel32);
    k_scan<<<1, 1>>>(out);
    k_scatter<<<NPAIR / 256, 256>>>(sel32);

    k_convX<<<(T_TOK * D_MODEL / 4) / 256, 256>>>(X);
    dim3 g1(D_FF / 32, D_MODEL / 32, N_EXP);
    k_convWt<<<g1, dim3(32, 8)>>>(W1, 0);
    dim3 g2(D_MODEL / 32, D_FF / 32, N_EXP);
    k_convWt<<<g2, dim3(32, 8)>>>(W2, 1);

    dim3 grid1(MAX_TILES, D_FF / 128);    // 72 x 16
    k_mma<true><<<grid1, 256, SMEM_GEMM>>>(out);
    dim3 grid2(MAX_TILES, D_MODEL / 128); // 72 x 4
    k_mma<false><<<grid2, 256, SMEM_GEMM>>>(out);
}

// round 5
// speedup vs baseline: 2.2613x; 1.2794x over previous
#include <cuda_runtime.h>
#include <cuda_fp16.h>
#include <math.h>
#include <stdint.h>

// Problem constants
#define T_TOK   4096
#define D_MODEL 512
#define D_FF    2048
#define N_EXP   8
#define K_ACT   2
#define NPAIR   (T_TOK * K_ACT)          // 8192
#define BM      128
#define MAX_TILES (NPAIR / BM + N_EXP)   // 72

// ---------------- device scratch ----------------
__device__ int g_is32;
__device__ int g_counts[N_EXP];
__device__ int g_fill[N_EXP];
__device__ int g_offsets[N_EXP + 1];
__device__ int g_pairs[NPAIR];
__device__ int g_tileExpert[MAX_TILES];
__device__ int g_tileRow[MAX_TILES];
__device__ int g_tileRows[MAX_TILES];
__device__ int g_numTiles;

__device__ __align__(16) __half g_Xhi[(size_t)T_TOK * D_MODEL];
__device__ __align__(16) __half g_Xlo[(size_t)T_TOK * D_MODEL];
__device__ __align__(16) __half g_W1t[(size_t)N_EXP * D_FF * D_MODEL]; // [e][n][k]
__device__ __align__(16) __half g_W2t[(size_t)N_EXP * D_MODEL * D_FF]; // [e][d][f]
__device__ __align__(16) __half g_Hhi[(size_t)NPAIR * D_FF];
__device__ __align__(16) __half g_Hlo[(size_t)NPAIR * D_FF];

// ---------------- PTX helpers (baseline sm_80+, compile under compute_103) ----
__device__ __forceinline__ uint32_t smem_u32(const void* p) {
    uint32_t a;
    asm("{ .reg .u64 t; cvta.to.shared.u64 t, %1; cvt.u32.u64 %0, t; }" : "=r"(a) : "l"(p));
    return a;
}
#define CP16(dst, src)  asm volatile("cp.async.cg.shared.global [%0], [%1], 16;" :: "r"(dst), "l"(src))
#define CP_COMMIT()     asm volatile("cp.async.commit_group;" ::: "memory")
#define CP_WAIT(n)      asm volatile("cp.async.wait_group %0;" :: "n"(n) : "memory")

__device__ __forceinline__ void ldsm_x4(uint32_t* r, uint32_t addr) {
    asm volatile("ldmatrix.sync.aligned.m8n8.x4.shared.b16 {%0,%1,%2,%3}, [%4];"
        : "=r"(r[0]), "=r"(r[1]), "=r"(r[2]), "=r"(r[3]) : "r"(addr));
}
__device__ __forceinline__ void mma16816(float* c, const uint32_t* a, uint32_t b0, uint32_t b1) {
    asm volatile("mma.sync.aligned.m16n8k16.row.col.f32.f16.f16.f32 "
        "{%0,%1,%2,%3}, {%4,%5,%6,%7}, {%8,%9}, {%0,%1,%2,%3};"
        : "+f"(c[0]), "+f"(c[1]), "+f"(c[2]), "+f"(c[3])
        : "r"(a[0]), "r"(a[1]), "r"(a[2]), "r"(a[3]), "r"(b0), "r"(b1));
}

// ---------------- routing (unchanged, proven) ----------------
__device__ __forceinline__ int pair_expert(const int* sel32, int p) {
    int e = g_is32 ? sel32[p] : sel32[2 * p];
    return min(max(e, 0), N_EXP - 1);
}
__global__ void k_init(const int* __restrict__ sel32) {
    int i = blockIdx.x * blockDim.x + threadIdx.x;
    if (i < N_EXP) { g_counts[i] = 0; g_fill[i] = 0; }
    if (i == 0) g_is32 = 0;
}
__global__ void k_detect(const int* __restrict__ sel32) {
    int i = blockIdx.x * blockDim.x + threadIdx.x;
    if (i < NPAIR / 2 && sel32[2 * i + 1] != 0) g_is32 = 1;
}
__global__ void k_hist(const int* __restrict__ sel32) {
    int p = blockIdx.x * blockDim.x + threadIdx.x;
    if (p < NPAIR) atomicAdd(&g_counts[pair_expert(sel32, p)], 1);
}
__global__ void k_scan(float* __restrict__ out) {
    int off = 0, nt = 0;
    for (int e = 0; e < N_EXP; e++) {
        g_offsets[e] = off;
        int c = g_counts[e];
        out[(size_t)NPAIR * D_MODEL + e] = (float)c / (float)T_TOK;
        for (int r0 = 0; r0 < c; r0 += BM) {
            g_tileExpert[nt] = e; g_tileRow[nt] = off + r0;
            g_tileRows[nt] = min(BM, c - r0); nt++;
        }
        off += c;
    }
    g_offsets[N_EXP] = off;
    g_numTiles = nt;
}
__global__ void k_scatter(const int* __restrict__ sel32) {
    int p = blockIdx.x * blockDim.x + threadIdx.x;
    if (p < NPAIR) {
        int e = pair_expert(sel32, p);
        g_pairs[g_offsets[e] + atomicAdd(&g_fill[e], 1)] = p;
    }
}

// ---------------- fp16 split conversions ----------------
__global__ void k_convX(const float* __restrict__ X) {
    int i = (blockIdx.x * 256 + threadIdx.x) * 4;
    float4 v = *(const float4*)(X + i);
    float f[4] = {v.x, v.y, v.z, v.w};
    __half h[4], l[4];
#pragma unroll
    for (int j = 0; j < 4; j++) {
        h[j] = __float2half_rn(f[j]);
        l[j] = __float2half_rn(f[j] - __half2float(h[j]));
    }
    *(uint2*)(g_Xhi + i) = *(uint2*)h;
    *(uint2*)(g_Xlo + i) = *(uint2*)l;
}

// transpose [R,C] fp32 -> [C,R] fp16, per expert (blockIdx.z)
__global__ void k_convWt(const float* __restrict__ Win, int isW2) {
    const int R = isW2 ? D_FF : D_MODEL;
    const int C = isW2 ? D_MODEL : D_FF;
    int e = blockIdx.z;
    const float* in = Win + (size_t)e * R * C;
    __half* oh = (isW2 ? g_W2t : g_W1t) + (size_t)e * R * C;
    __shared__ float tile[32][33];
    int c0 = blockIdx.x * 32, r0 = blockIdx.y * 32;
    int tx = threadIdx.x, ty = threadIdx.y; // (32, 8)
#pragma unroll
    for (int j = 0; j < 4; j++)
        tile[ty * 4 + j][tx] = in[(size_t)(r0 + ty * 4 + j) * C + c0 + tx];
    __syncthreads();
#pragma unroll
    for (int j = 0; j < 4; j++)
        oh[(size_t)(c0 + ty * 4 + j) * R + r0 + tx] = __float2half_rn(tile[tx][ty * 4 + j]);
}

__device__ __forceinline__ float gelu_exact(float v) {
    return 0.5f * v * (1.0f + erff(v * 0.70710678118654752f));
}

// ---------------- fp16 2-term GEMM via mma.sync ----------------
// C = (Ahi + Alo) @ B, fp16 operands, fp32 accum. CTA tile 128x128, BK=64,
// 3-stage cp.async pipeline, 8 warps (4M x 2N).
// Stage: Ahi | Alo | B, each 128 rows x 144B (128B data + 16B pad).
#define ROWB   144
#define ARR_SZ (128 * ROWB)        // 18432 B
#define STG_SZ (3 * ARR_SZ)        // 55296 B
#define NSTG   3
#define SMEM_GEMM (NSTG * STG_SZ)  // 165888 B

template<bool G1>
__global__ __launch_bounds__(256, 1) void k_mma(float* __restrict__ out) {
    constexpr int KDIM = G1 ? D_MODEL : D_FF;
    constexpr int NCH  = KDIM / 64;

    int tile = blockIdx.x;
    if (tile >= g_numTiles) return;
    int e    = g_tileExpert[tile];
    int row0 = g_tileRow[tile];
    int rows = g_tileRows[tile];
    int n0   = blockIdx.y * 128;

    extern __shared__ __align__(128) char smem[];
    uint32_t sb = smem_u32(smem);
    __shared__ int s_rows[128];
    __shared__ int s_pair[128];

    int tid = threadIdx.x;
    int wid = tid >> 5, l = tid & 31;

    if (tid < 128) {
        int rr = min(tid, rows - 1);
        int p = g_pairs[row0 + rr];
        s_pair[tid] = p;
        s_rows[tid] = G1 ? (p >> 1) : (row0 + rr);
    }
    __syncthreads();

    const __half* Ahi = G1 ? g_Xhi : g_Hhi;
    const __half* Alo = G1 ? g_Xlo : g_Hlo;
    const size_t wstride = (size_t)D_FF * D_MODEL;
    const __half* Bw = (G1 ? g_W1t : g_W2t) + (size_t)e * wstride;

    // per-thread load slice: row = tid/2, half = tid&1 covers 64B (32 fp16)
    int lrow = tid >> 1, half = tid & 1;
    const __half* aHp = Ahi + (size_t)s_rows[lrow] * KDIM + half * 32;
    const __half* aLp = Alo + (size_t)s_rows[lrow] * KDIM + half * 32;
    const __half* bWp = Bw + (size_t)(n0 + lrow) * KDIM + half * 32;
    uint32_t dOff = (uint32_t)(lrow * ROWB + half * 64);

#define LOAD_STAGE(sidx, k0)                                     \
    {                                                            \
        uint32_t _st = sb + (uint32_t)(sidx) * STG_SZ + dOff;    \
        _Pragma("unroll")                                        \
        for (int i = 0; i < 4; i++) {                            \
            CP16(_st +            i * 16, aHp + (k0) + i * 8);   \
            CP16(_st +   ARR_SZ + i * 16, aLp + (k0) + i * 8);   \
            CP16(_st + 2*ARR_SZ + i * 16, bWp + (k0) + i * 8);   \
        }                                                        \
        CP_COMMIT();                                             \
    }

    int warp_m = (wid >> 1) * 32;
    int warp_n = (wid & 1) * 64;

    float acc[2][8][4];
#pragma unroll
    for (int i = 0; i < 2; i++)
#pragma unroll
        for (int j = 0; j < 8; j++)
#pragma unroll
            for (int q = 0; q < 4; q++) acc[i][j][q] = 0.0f;

    uint32_t aLane = (uint32_t)((warp_m + (l & 15)) * ROWB + (l >> 4) * 16);
    uint32_t bLane = (uint32_t)(2 * ARR_SZ + (warp_n + (l & 15)) * ROWB + (l >> 4) * 16);

    LOAD_STAGE(0, 0);
    LOAD_STAGE(1, 64);

    int s = 0;
    for (int c = 0; c < NCH; c++) {
        CP_WAIT(1);
        __syncthreads();
        if (c + 2 < NCH) {
            int sn = s + 2; if (sn >= NSTG) sn -= NSTG;
            LOAD_STAGE(sn, (c + 2) * 64);
        }
        uint32_t st = sb + (uint32_t)s * STG_SZ;
#pragma unroll
        for (int kk = 0; kk < 4; kk++) {
            uint32_t ah[2][4], al[2][4], bw[4][4];
#pragma unroll
            for (int mb = 0; mb < 2; mb++) {
                ldsm_x4(ah[mb], st + aLane + (uint32_t)(mb * 16 * ROWB + kk * 32));
                ldsm_x4(al[mb], st + ARR_SZ + aLane + (uint32_t)(mb * 16 * ROWB + kk * 32));
            }
#pragma unroll
            for (int nb2 = 0; nb2 < 4; nb2++)
                ldsm_x4(bw[nb2], st + bLane + (uint32_t)(nb2 * 16 * ROWB + kk * 32));
#pragma unroll
            for (int mb = 0; mb < 2; mb++)
#pragma unroll
                for (int nb = 0; nb < 8; nb++) {
                    int nb2 = nb >> 1, sel = nb & 1;
                    mma16816(acc[mb][nb], ah[mb], bw[nb2][sel], bw[nb2][sel + 2]);
                    mma16816(acc[mb][nb], al[mb], bw[nb2][sel], bw[nb2][sel + 2]);
                }
        }
        __syncthreads();
        s++; if (s >= NSTG) s = 0;
    }

    // epilogue
#pragma unroll
    for (int mb = 0; mb < 2; mb++)
#pragma unroll
        for (int nb = 0; nb < 8; nb++) {
            int rbase = warp_m + mb * 16 + (l >> 2);
            int col   = warp_n + nb * 8 + (l & 3) * 2;
#pragma unroll
            for (int p = 0; p < 2; p++) {
                int m = rbase + p * 8;
                if (m < rows) {
                    float y0 = acc[mb][nb][2 * p];
                    float y1 = acc[mb][nb][2 * p + 1];
                    if (G1) {
                        y0 = gelu_exact(y0);
                        y1 = gelu_exact(y1);
                        __half2 hh, ll;
                        hh.x = __float2half_rn(y0);
                        hh.y = __float2half_rn(y1);
                        ll.x = __float2half_rn(y0 - __half2float(hh.x));
                        ll.y = __float2half_rn(y1 - __half2float(hh.y));
                        size_t o = (size_t)(row0 + m) * D_FF + n0 + col;
                        *(uint32_t*)(g_Hhi + o) = *(uint32_t*)&hh;
                        *(uint32_t*)(g_Hlo + o) = *(uint32_t*)&ll;
                    } else {
                        size_t o = (size_t)s_pair[m] * D_MODEL + n0 + col;
                        float2 v; v.x = y0; v.y = y1;
                        *(float2*)(out + o) = v;
                    }
                }
            }
        }
#undef LOAD_STAGE
}

// ---------------- launch ----------------
extern "C" void kernel_launch(void* const* d_in, const int* in_sizes, int n_in,
                              void* d_out, int out_size) {
    const float* X     = (const float*)d_in[0];
    const int*   sel32 = (const int*)d_in[1];
    const float* W1    = (const float*)d_in[3];
    const float* W2    = (const float*)d_in[4];
    float*       out   = (float*)d_out;

    cudaFuncSetAttribute((const void*)k_mma<true>,  cudaFuncAttributeMaxDynamicSharedMemorySize, SMEM_GEMM);
    cudaFuncSetAttribute((const void*)k_mma<false>, cudaFuncAttributeMaxDynamicSharedMemorySize, SMEM_GEMM);

    k_init<<<1, 32>>>(sel32);
    k_detect<<<(NPAIR / 2 + 255) / 256, 256>>>(sel32);
    k_hist<<<NPAIR / 256, 256>>>(sel32);
    k_scan<<<1, 1>>>(out);
    k_scatter<<<NPAIR / 256, 256>>>(sel32);

    k_convX<<<(T_TOK * D_MODEL / 4) / 256, 256>>>(X);
    dim3 g1(D_FF / 32, D_MODEL / 32, N_EXP);
    k_convWt<<<g1, dim3(32, 8)>>>(W1, 0);
    dim3 g2(D_MODEL / 32, D_FF / 32, N_EXP);
    k_convWt<<<g2, dim3(32, 8)>>>(W2, 1);

    dim3 grid1(MAX_TILES, D_FF / 128);    // 72 x 16
    k_mma<true><<<grid1, 256, SMEM_GEMM>>>(out);
    dim3 grid2(MAX_TILES, D_MODEL / 128); // 72 x 4
    k_mma<false><<<grid2, 256, SMEM_GEMM>>>(out);
}

// round 6
// speedup vs baseline: 2.7998x; 1.2381x over previous
#include <cuda_runtime.h>
#include <cuda_fp16.h>
#include <math.h>
#include <stdint.h>

// Problem constants
#define T_TOK   4096
#define D_MODEL 512
#define D_FF    2048
#define N_EXP   8
#define K_ACT   2
#define NPAIR   (T_TOK * K_ACT)          // 8192
#define BM      128
#define MAX_TILES (NPAIR / BM + N_EXP)   // 72

// ---------------- device scratch ----------------
__device__ int g_is32;
__device__ int g_counts[N_EXP];
__device__ int g_fill[N_EXP];
__device__ int g_offsets[N_EXP + 1];
__device__ int g_pairs[NPAIR];
__device__ int g_tileExpert[MAX_TILES];
__device__ int g_tileRow[MAX_TILES];
__device__ int g_tileRows[MAX_TILES];
__device__ int g_numTiles;

__device__ __align__(16) __half g_Xhi[(size_t)T_TOK * D_MODEL];
__device__ __align__(16) __half g_Xlo[(size_t)T_TOK * D_MODEL];
__device__ __align__(16) __half g_W1t[(size_t)N_EXP * D_FF * D_MODEL]; // [e][n][k]
__device__ __align__(16) __half g_W2t[(size_t)N_EXP * D_MODEL * D_FF]; // [e][d][f]
__device__ __align__(16) __half g_Ht[(size_t)NPAIR * D_FF];            // gelu(X@W1), fp16

// ---------------- PTX helpers (baseline sm_80+, compile under compute_103) ----
__device__ __forceinline__ uint32_t smem_u32(const void* p) {
    uint32_t a;
    asm("{ .reg .u64 t; cvta.to.shared.u64 t, %1; cvt.u32.u64 %0, t; }" : "=r"(a) : "l"(p));
    return a;
}
#define CP16(dst, src)  asm volatile("cp.async.cg.shared.global [%0], [%1], 16;" :: "r"(dst), "l"(src))
#define CP_COMMIT()     asm volatile("cp.async.commit_group;" ::: "memory")
#define CP_WAIT(n)      asm volatile("cp.async.wait_group %0;" :: "n"(n) : "memory")

__device__ __forceinline__ void ldsm_x4(uint32_t* r, uint32_t addr) {
    asm volatile("ldmatrix.sync.aligned.m8n8.x4.shared.b16 {%0,%1,%2,%3}, [%4];"
        : "=r"(r[0]), "=r"(r[1]), "=r"(r[2]), "=r"(r[3]) : "r"(addr));
}
__device__ __forceinline__ void mma16816(float* c, const uint32_t* a, uint32_t b0, uint32_t b1) {
    asm volatile("mma.sync.aligned.m16n8k16.row.col.f32.f16.f16.f32 "
        "{%0,%1,%2,%3}, {%4,%5,%6,%7}, {%8,%9}, {%0,%1,%2,%3};"
        : "+f"(c[0]), "+f"(c[1]), "+f"(c[2]), "+f"(c[3])
        : "r"(a[0]), "r"(a[1]), "r"(a[2]), "r"(a[3]), "r"(b0), "r"(b1));
}

// ---------------- routing ----------------
__device__ __forceinline__ int pair_expert(const int* sel32, int p) {
    int e = g_is32 ? sel32[p] : sel32[2 * p];
    return min(max(e, 0), N_EXP - 1);
}
// init + dtype detect in one single-block kernel
__global__ void k_init(const int* __restrict__ sel32) {
    int t = threadIdx.x;
    if (t < N_EXP) { g_counts[t] = 0; g_fill[t] = 0; }
    if (t == 0) g_is32 = 0;
    __syncthreads();
    int any = 0;
    for (int i = t; i < NPAIR / 2; i += 256) any |= sel32[2 * i + 1];
    if (any) atomicOr(&g_is32, 1);
}
__global__ void k_hist(const int* __restrict__ sel32) {
    int p = blockIdx.x * blockDim.x + threadIdx.x;
    if (p < NPAIR) atomicAdd(&g_counts[pair_expert(sel32, p)], 1);
}
__global__ void k_scan(float* __restrict__ out) {
    int off = 0, nt = 0;
    for (int e = 0; e < N_EXP; e++) {
        g_offsets[e] = off;
        int c = g_counts[e];
        out[(size_t)NPAIR * D_MODEL + e] = (float)c / (float)T_TOK;
        for (int r0 = 0; r0 < c; r0 += BM) {
            g_tileExpert[nt] = e; g_tileRow[nt] = off + r0;
            g_tileRows[nt] = min(BM, c - r0); nt++;
        }
        off += c;
    }
    g_offsets[N_EXP] = off;
    g_numTiles = nt;
}
__global__ void k_scatter(const int* __restrict__ sel32) {
    int p = blockIdx.x * blockDim.x + threadIdx.x;
    if (p < NPAIR) {
        int e = pair_expert(sel32, p);
        g_pairs[g_offsets[e] + atomicAdd(&g_fill[e], 1)] = p;
    }
}

// ---------------- conversions ----------------
__global__ void k_convX(const float* __restrict__ X) {
    int i = (blockIdx.x * 256 + threadIdx.x) * 4;
    float4 v = *(const float4*)(X + i);
    float f[4] = {v.x, v.y, v.z, v.w};
    __half h[4], l[4];
#pragma unroll
    for (int j = 0; j < 4; j++) {
        h[j] = __float2half_rn(f[j]);
        l[j] = __float2half_rn(f[j] - __half2float(h[j]));
    }
    *(uint2*)(g_Xhi + i) = *(uint2*)h;
    *(uint2*)(g_Xlo + i) = *(uint2*)l;
}

// transpose [R,C] fp32 -> [C,R] fp16, per expert (blockIdx.z)
__global__ void k_convWt(const float* __restrict__ Win, int isW2) {
    const int R = isW2 ? D_FF : D_MODEL;
    const int C = isW2 ? D_MODEL : D_FF;
    int e = blockIdx.z;
    const float* in = Win + (size_t)e * R * C;
    __half* oh = (isW2 ? g_W2t : g_W1t) + (size_t)e * R * C;
    __shared__ float tile[32][33];
    int c0 = blockIdx.x * 32, r0 = blockIdx.y * 32;
    int tx = threadIdx.x, ty = threadIdx.y; // (32, 8)
#pragma unroll
    for (int j = 0; j < 4; j++)
        tile[ty * 4 + j][tx] = in[(size_t)(r0 + ty * 4 + j) * C + c0 + tx];
    __syncthreads();
#pragma unroll
    for (int j = 0; j < 4; j++)
        oh[(size_t)(c0 + ty * 4 + j) * R + r0 + tx] = __float2half_rn(tile[tx][ty * 4 + j]);
}

__device__ __forceinline__ float gelu_exact(float v) {
    return 0.5f * v * (1.0f + erff(v * 0.70710678118654752f));
}

// ---------------- GEMM via mma.sync (HMMA) ----------------
// CTA tile 128(M) x 256(N), BK=64, double-buffered cp.async.
// 8 warps: warp tile 32(M) x 128(N).
// GEMM1 (G1): C = (Xhi + Xlo) @ W1  -> gelu -> g_Ht   (2-term A)
// GEMM2:      C = Ht @ W2           -> out           (1-term)
#define ROWB   144
#define ARR_A  (128 * ROWB)                 // 18432 B (one 128-row A array)
#define ARR_B  (256 * ROWB)                 // 36864 B (256-row B array)
#define STG1   (2 * ARR_A + ARR_B)          // 73728
#define STG2   (ARR_A + ARR_B)              // 55296
#define SMEM_G1 (2 * STG1)                  // 147456
#define SMEM_G2 (2 * STG2)                  // 110592

template<bool G1>
__global__ __launch_bounds__(256, 1) void k_mma(float* __restrict__ out) {
    constexpr int KDIM  = G1 ? D_MODEL : D_FF;
    constexpr int NCH   = KDIM / 64;
    constexpr uint32_t STG   = G1 ? STG1 : STG2;
    constexpr uint32_t OFF_B = G1 ? 2 * ARR_A : ARR_A;

    int tile = blockIdx.x;
    if (tile >= g_numTiles) return;
    int e    = g_tileExpert[tile];
    int row0 = g_tileRow[tile];
    int rows = g_tileRows[tile];
    int n0   = blockIdx.y * 256;

    extern __shared__ __align__(128) char smem[];
    uint32_t sb = smem_u32(smem);
    __shared__ int s_rows[128];
    __shared__ int s_pair[128];

    int tid = threadIdx.x;
    int wid = tid >> 5, l = tid & 31;

    if (tid < 128) {
        int rr = min(tid, rows - 1);
        int p = g_pairs[row0 + rr];
        s_pair[tid] = p;
        s_rows[tid] = G1 ? (p >> 1) : (row0 + rr);
    }
    __syncthreads();

    const size_t wstride = (size_t)D_FF * D_MODEL;
    const __half* Bw = (G1 ? g_W1t : g_W2t) + (size_t)e * wstride;

    // ---- per-thread load slices ----
    // B: 256 rows, one row per thread (8 CP16 of 16B, 128B data per chunk-row)
    const __half* bWp = Bw + (size_t)(n0 + tid) * KDIM;
    uint32_t dOffB = OFF_B + (uint32_t)tid * ROWB;
    // A (G1): threads 0-127 -> Ahi row tid; threads 128-255 -> Alo row tid-128
    // A (G2): 256 threads, half-row each (4 CP16)
    const __half* aP;
    uint32_t dOffA;
    if (G1) {
        int r = tid & 127;
        const __half* base = (tid < 128) ? g_Xhi : g_Xlo;
        aP = base + (size_t)s_rows[r] * KDIM;
        dOffA = (tid < 128 ? 0u : (uint32_t)ARR_A) + (uint32_t)r * ROWB;
    } else {
        int r = tid >> 1, half = tid & 1;
        aP = g_Ht + (size_t)s_rows[r] * KDIM + half * 32;
        dOffA = (uint32_t)r * ROWB + (uint32_t)half * 64;
    }

#define LOAD_STAGE(sidx, k0)                                           \
    {                                                                  \
        uint32_t _s = sb + (uint32_t)(sidx) * STG;                     \
        if (G1) {                                                      \
            _Pragma("unroll")                                          \
            for (int i = 0; i < 8; i++)                                \
                CP16(_s + dOffA + i * 16, aP + (k0) + i * 8);          \
        } else {                                                       \
            _Pragma("unroll")                                          \
            for (int i = 0; i < 4; i++)                                \
                CP16(_s + dOffA + i * 16, aP + (k0) + i * 8);          \
        }                                                              \
        _Pragma("unroll")                                              \
        for (int i = 0; i < 8; i++)                                    \
            CP16(_s + dOffB + i * 16, bWp + (k0) + i * 8);             \
        CP_COMMIT();                                                   \
    }

    int warp_m = (wid >> 1) * 32;     // 0,32,64,96
    int warp_n = (wid & 1) * 128;     // 0,128

    float acc[2][16][4];
#pragma unroll
    for (int i = 0; i < 2; i++)
#pragma unroll
        for (int j = 0; j < 16; j++)
#pragma unroll
            for (int q = 0; q < 4; q++) acc[i][j][q] = 0.0f;

    uint32_t aLane = (uint32_t)((warp_m + (l & 15)) * ROWB + (l >> 4) * 16);
    uint32_t bLane = OFF_B + (uint32_t)((warp_n + (l & 15)) * ROWB + (l >> 4) * 16);

    LOAD_STAGE(0, 0);
    int buf = 0;
    for (int c = 0; c < NCH; c++) {
        if (c + 1 < NCH) { LOAD_STAGE(buf ^ 1, (c + 1) * 64); CP_WAIT(1); }
        else             { CP_WAIT(0); }
        __syncthreads();
        uint32_t st = sb + (uint32_t)buf * STG;
#pragma unroll
        for (int kk = 0; kk < 4; kk++) {
            uint32_t ah[2][4], al[2][4], bw[8][4];
#pragma unroll
            for (int mb = 0; mb < 2; mb++) {
                ldsm_x4(ah[mb], st + aLane + (uint32_t)(mb * 16 * ROWB + kk * 32));
                if (G1)
                    ldsm_x4(al[mb], st + ARR_A + aLane + (uint32_t)(mb * 16 * ROWB + kk * 32));
            }
#pragma unroll
            for (int nb2 = 0; nb2 < 8; nb2++)
                ldsm_x4(bw[nb2], st + bLane + (uint32_t)(nb2 * 16 * ROWB + kk * 32));
#pragma unroll
            for (int mb = 0; mb < 2; mb++)
#pragma unroll
                for (int nb = 0; nb < 16; nb++) {
                    int nb2 = nb >> 1, sel = nb & 1;
                    mma16816(acc[mb][nb], ah[mb], bw[nb2][sel], bw[nb2][sel + 2]);
                    if (G1)
                        mma16816(acc[mb][nb], al[mb], bw[nb2][sel], bw[nb2][sel + 2]);
                }
        }
        __syncthreads();
        buf ^= 1;
    }

    // epilogue
#pragma unroll
    for (int mb = 0; mb < 2; mb++)
#pragma unroll
        for (int nb = 0; nb < 16; nb++) {
            int rbase = warp_m + mb * 16 + (l >> 2);
            int col   = warp_n + nb * 8 + (l & 3) * 2;
#pragma unroll
            for (int p = 0; p < 2; p++) {
                int m = rbase + p * 8;
                if (m < rows) {
                    float y0 = acc[mb][nb][2 * p];
                    float y1 = acc[mb][nb][2 * p + 1];
                    if (G1) {
                        __half2 hh;
                        hh.x = __float2half_rn(gelu_exact(y0));
                        hh.y = __float2half_rn(gelu_exact(y1));
                        size_t o = (size_t)(row0 + m) * D_FF + n0 + col;
                        *(uint32_t*)(g_Ht + o) = *(uint32_t*)&hh;
                    } else {
                        size_t o = (size_t)s_pair[m] * D_MODEL + n0 + col;
                        float2 v; v.x = y0; v.y = y1;
                        *(float2*)(out + o) = v;
                    }
                }
            }
        }
#undef LOAD_STAGE
}

// ---------------- launch ----------------
extern "C" void kernel_launch(void* const* d_in, const int* in_sizes, int n_in,
                              void* d_out, int out_size) {
    const float* X     = (const float*)d_in[0];
    const int*   sel32 = (const int*)d_in[1];
    const float* W1    = (const float*)d_in[3];
    const float* W2    = (const float*)d_in[4];
    float*       out   = (float*)d_out;

    cudaFuncSetAttribute((const void*)k_mma<true>,  cudaFuncAttributeMaxDynamicSharedMemorySize, SMEM_G1);
    cudaFuncSetAttribute((const void*)k_mma<false>, cudaFuncAttributeMaxDynamicSharedMemorySize, SMEM_G2);

    k_init<<<1, 256>>>(sel32);
    k_hist<<<NPAIR / 256, 256>>>(sel32);
    k_scan<<<1, 1>>>(out);
    k_scatter<<<NPAIR / 256, 256>>>(sel32);

    k_convX<<<(T_TOK * D_MODEL / 4) / 256, 256>>>(X);
    dim3 g1(D_FF / 32, D_MODEL / 32, N_EXP);
    k_convWt<<<g1, dim3(32, 8)>>>(W1, 0);
    dim3 g2(D_MODEL / 32, D_FF / 32, N_EXP);
    k_convWt<<<g2, dim3(32, 8)>>>(W2, 1);

    dim3 grid1(MAX_TILES, D_FF / 256);    // 72 x 8 = 576 CTAs
    k_mma<true><<<grid1, 256, SMEM_G1>>>(out);
    dim3 grid2(MAX_TILES, D_MODEL / 256); // 72 x 2 = 144 CTAs
    k_mma<false><<<grid2, 256, SMEM_G2>>>(out);
}

// round 7
// speedup vs baseline: 3.5962x; 1.2844x over previous
#include <cuda_runtime.h>
#include <cuda_fp16.h>
#include <math.h>
#include <stdint.h>

// Problem constants
#define T_TOK   4096
#define D_MODEL 512
#define D_FF    2048
#define N_EXP   8
#define K_ACT   2
#define NPAIR   (T_TOK * K_ACT)          // 8192
#define BM      128
#define MAX_TILES (NPAIR / BM + N_EXP)   // 72

// ---------------- device scratch ----------------
__device__ int g_pairs[NPAIR];
__device__ int g_tileExpert[MAX_TILES];
__device__ int g_tileRow[MAX_TILES];
__device__ int g_tileRows[MAX_TILES];
__device__ int g_numTiles;

__device__ __align__(16) __half g_Xh [(size_t)T_TOK * D_MODEL];
__device__ __align__(16) __half g_W1t[(size_t)N_EXP * D_FF * D_MODEL]; // [e][n][k]
__device__ __align__(16) __half g_W2t[(size_t)N_EXP * D_MODEL * D_FF]; // [e][d][f]
__device__ __align__(16) __half g_Ht [(size_t)NPAIR * D_FF];           // gelu(X@W1)

// ---------------- PTX helpers (baseline sm_80+) ----------------
__device__ __forceinline__ uint32_t smem_u32(const void* p) {
    uint32_t a;
    asm("{ .reg .u64 t; cvta.to.shared.u64 t, %1; cvt.u32.u64 %0, t; }" : "=r"(a) : "l"(p));
    return a;
}
#define CP16(dst, src)  asm volatile("cp.async.cg.shared.global [%0], [%1], 16;" :: "r"(dst), "l"(src))
#define CP_COMMIT()     asm volatile("cp.async.commit_group;" ::: "memory")
#define CP_WAIT(n)      asm volatile("cp.async.wait_group %0;" :: "n"(n) : "memory")

__device__ __forceinline__ void ldsm_x4(uint32_t* r, uint32_t addr) {
    asm volatile("ldmatrix.sync.aligned.m8n8.x4.shared.b16 {%0,%1,%2,%3}, [%4];"
        : "=r"(r[0]), "=r"(r[1]), "=r"(r[2]), "=r"(r[3]) : "r"(addr));
}
__device__ __forceinline__ void mma16816(float* c, const uint32_t* a, uint32_t b0, uint32_t b1) {
    asm volatile("mma.sync.aligned.m16n8k16.row.col.f32.f16.f16.f32 "
        "{%0,%1,%2,%3}, {%4,%5,%6,%7}, {%8,%9}, {%0,%1,%2,%3};"
        : "+f"(c[0]), "+f"(c[1]), "+f"(c[2]), "+f"(c[3])
        : "r"(a[0]), "r"(a[1]), "r"(a[2]), "r"(a[3]), "r"(b0), "r"(b1));
}

// ---------------- fused routing: init+detect+hist+scan+scatter, 1 block ----
__global__ void k_route(const int* __restrict__ sel32, float* __restrict__ out) {
    __shared__ int sh_cnt[N_EXP];
    __shared__ int sh_off[N_EXP];
    int t = threadIdx.x;  // 256
    if (t < N_EXP) sh_cnt[t] = 0;
    __syncthreads();
    // dtype detect: int64 values 0..7 have zero high words at odd indices
    int any = 0;
    for (int i = t; i < NPAIR / 2; i += 256) any |= sel32[2 * i + 1];
    int is32 = __syncthreads_or(any);
    // histogram (shared atomics)
    for (int p = t; p < NPAIR; p += 256) {
        int e = is32 ? sel32[p] : sel32[2 * p];
        e = min(max(e, 0), N_EXP - 1);
        atomicAdd(&sh_cnt[e], 1);
    }
    __syncthreads();
    if (t == 0) {
        int off = 0, nt = 0;
        for (int e = 0; e < N_EXP; e++) {
            sh_off[e] = off;
            int c = sh_cnt[e];
            out[(size_t)NPAIR * D_MODEL + e] = (float)c / (float)T_TOK;
            for (int r0 = 0; r0 < c; r0 += BM) {
                g_tileExpert[nt] = e; g_tileRow[nt] = off + r0;
                g_tileRows[nt] = min(BM, c - r0); nt++;
            }
            off += c;
        }
        g_numTiles = nt;
    }
    __syncthreads();
    if (t < N_EXP) sh_cnt[t] = 0;  // reuse as fill counters
    __syncthreads();
    for (int p = t; p < NPAIR; p += 256) {
        int e = is32 ? sel32[p] : sel32[2 * p];
        e = min(max(e, 0), N_EXP - 1);
        int pos = sh_off[e] + atomicAdd(&sh_cnt[e], 1);
        g_pairs[pos] = p;  // order within expert is irrelevant to output bits
    }
}

// ---------------- conversions ----------------
__global__ void k_convX(const float* __restrict__ X) {
    int i = (blockIdx.x * 256 + threadIdx.x) * 4;
    float4 v = *(const float4*)(X + i);
    __half h[4];
    h[0] = __float2half_rn(v.x); h[1] = __float2half_rn(v.y);
    h[2] = __float2half_rn(v.z); h[3] = __float2half_rn(v.w);
    *(uint2*)(g_Xh + i) = *(uint2*)h;
}

// transpose [R,C] fp32 -> [C,R] fp16, per expert (blockIdx.z)
__global__ void k_convWt(const float* __restrict__ Win, int isW2) {
    const int R = isW2 ? D_FF : D_MODEL;
    const int C = isW2 ? D_MODEL : D_FF;
    int e = blockIdx.z;
    const float* in = Win + (size_t)e * R * C;
    __half* oh = (isW2 ? g_W2t : g_W1t) + (size_t)e * R * C;
    __shared__ float tile[32][33];
    int c0 = blockIdx.x * 32, r0 = blockIdx.y * 32;
    int tx = threadIdx.x, ty = threadIdx.y; // (32, 8)
#pragma unroll
    for (int j = 0; j < 4; j++)
        tile[ty * 4 + j][tx] = in[(size_t)(r0 + ty * 4 + j) * C + c0 + tx];
    __syncthreads();
#pragma unroll
    for (int j = 0; j < 4; j++)
        oh[(size_t)(c0 + ty * 4 + j) * R + r0 + tx] = __float2half_rn(tile[tx][ty * 4 + j]);
}

__device__ __forceinline__ float gelu_exact(float v) {
    return 0.5f * v * (1.0f + erff(v * 0.70710678118654752f));
}

// ---------------- 1-term fp16 GEMM via mma.sync ----------------
// CTA tile 128(M) x 256(N), BK=64, 3-stage cp.async pipeline.
// 8 warps: warp tile 32(M) x 128(N).
// G1: Ht = gelu(Xh @ W1t^T);  G2: out = Ht @ W2t^T (pair-scattered rows)
#define ROWB   144
#define ARR_A  (128 * ROWB)            // 18432 B
#define ARR_B  (256 * ROWB)            // 36864 B
#define STG    (ARR_A + ARR_B)         // 55296 B
#define NSTG   3
#define SMEM_GEMM (NSTG * STG)         // 165888 B

template<bool G1>
__global__ __launch_bounds__(256, 1) void k_mma(float* __restrict__ out) {
    constexpr int KDIM = G1 ? D_MODEL : D_FF;
    constexpr int NCH  = KDIM / 64;

    int tile = blockIdx.x;
    if (tile >= g_numTiles) return;
    int e    = g_tileExpert[tile];
    int row0 = g_tileRow[tile];
    int rows = g_tileRows[tile];
    int n0   = blockIdx.y * 256;

    extern __shared__ __align__(128) char smem[];
    uint32_t sb = smem_u32(smem);
    __shared__ int s_rows[128];
    __shared__ int s_pair[128];

    int tid = threadIdx.x;
    int wid = tid >> 5, l = tid & 31;

    if (tid < 128) {
        int rr = min(tid, rows - 1);
        int p = g_pairs[row0 + rr];
        s_pair[tid] = p;
        s_rows[tid] = G1 ? (p >> 1) : (row0 + rr);
    }
    __syncthreads();

    const size_t wstride = (size_t)D_FF * D_MODEL;
    const __half* Bw = (G1 ? g_W1t : g_W2t) + (size_t)e * wstride;
    const __half* Asrc = G1 ? g_Xh : g_Ht;

    // per-thread load slices
    int r = tid >> 1, half = tid & 1;
    const __half* aP = Asrc + (size_t)s_rows[r] * KDIM + half * 32;
    uint32_t dOffA = (uint32_t)r * ROWB + (uint32_t)half * 64;
    const __half* bWp = Bw + (size_t)(n0 + tid) * KDIM;
    uint32_t dOffB = (uint32_t)ARR_A + (uint32_t)tid * ROWB;

#define LOAD_STAGE(sidx, k0)                                     \
    {                                                            \
        uint32_t _s = sb + (uint32_t)(sidx) * STG;               \
        _Pragma("unroll")                                        \
        for (int i = 0; i < 4; i++)                              \
            CP16(_s + dOffA + i * 16, aP + (k0) + i * 8);        \
        _Pragma("unroll")                                        \
        for (int i = 0; i < 8; i++)                              \
            CP16(_s + dOffB + i * 16, bWp + (k0) + i * 8);       \
        CP_COMMIT();                                             \
    }

    int warp_m = (wid >> 1) * 32;     // 0,32,64,96
    int warp_n = (wid & 1) * 128;     // 0,128

    float acc[2][16][4];
#pragma unroll
    for (int i = 0; i < 2; i++)
#pragma unroll
        for (int j = 0; j < 16; j++)
#pragma unroll
            for (int q = 0; q < 4; q++) acc[i][j][q] = 0.0f;

    uint32_t aLane = (uint32_t)((warp_m + (l & 15)) * ROWB + (l >> 4) * 16);
    uint32_t bLane = (uint32_t)ARR_A + (uint32_t)((warp_n + (l & 15)) * ROWB + (l >> 4) * 16);

    LOAD_STAGE(0, 0);
    LOAD_STAGE(1, 64);

    int s = 0;
    for (int c = 0; c < NCH; c++) {
        if (c + 2 < NCH) {
            int sn = s + 2; if (sn >= NSTG) sn -= NSTG;
            LOAD_STAGE(sn, (c + 2) * 64);
        }
        if (c <= NCH - 3)      CP_WAIT(2);
        else if (c == NCH - 2) CP_WAIT(1);
        else                   CP_WAIT(0);
        __syncthreads();
        uint32_t st = sb + (uint32_t)s * STG;
#pragma unroll
        for (int kk = 0; kk < 4; kk++) {
            uint32_t ah[2][4], bw[8][4];
#pragma unroll
            for (int mb = 0; mb < 2; mb++)
                ldsm_x4(ah[mb], st + aLane + (uint32_t)(mb * 16 * ROWB + kk * 32));
#pragma unroll
            for (int nb2 = 0; nb2 < 8; nb2++)
                ldsm_x4(bw[nb2], st + bLane + (uint32_t)(nb2 * 16 * ROWB + kk * 32));
#pragma unroll
            for (int mb = 0; mb < 2; mb++)
#pragma unroll
                for (int nb = 0; nb < 16; nb++) {
                    int nb2 = nb >> 1, sel = nb & 1;
                    mma16816(acc[mb][nb], ah[mb], bw[nb2][sel], bw[nb2][sel + 2]);
                }
        }
        __syncthreads();
        s++; if (s >= NSTG) s = 0;
    }

    // epilogue
#pragma unroll
    for (int mb = 0; mb < 2; mb++)
#pragma unroll
        for (int nb = 0; nb < 16; nb++) {
            int rbase = warp_m + mb * 16 + (l >> 2);
            int col   = warp_n + nb * 8 + (l & 3) * 2;
#pragma unroll
            for (int p = 0; p < 2; p++) {
                int m = rbase + p * 8;
                if (m < rows) {
                    float y0 = acc[mb][nb][2 * p];
                    float y1 = acc[mb][nb][2 * p + 1];
                    if (G1) {
                        __half2 hh;
                        hh.x = __float2half_rn(gelu_exact(y0));
                        hh.y = __float2half_rn(gelu_exact(y1));
                        size_t o = (size_t)(row0 + m) * D_FF + n0 + col;
                        *(uint32_t*)(g_Ht + o) = *(uint32_t*)&hh;
                    } else {
                        size_t o = (size_t)s_pair[m] * D_MODEL + n0 + col;
                        float2 v; v.x = y0; v.y = y1;
                        *(float2*)(out + o) = v;
                    }
                }
            }
        }
#undef LOAD_STAGE
}

// ---------------- launch ----------------
extern "C" void kernel_launch(void* const* d_in, const int* in_sizes, int n_in,
                              void* d_out, int out_size) {
    const float* X     = (const float*)d_in[0];
    const int*   sel32 = (const int*)d_in[1];
    const float* W1    = (const float*)d_in[3];
    const float* W2    = (const float*)d_in[4];
    float*       out   = (float*)d_out;

    cudaFuncSetAttribute((const void*)k_mma<true>,  cudaFuncAttributeMaxDynamicSharedMemorySize, SMEM_GEMM);
    cudaFuncSetAttribute((const void*)k_mma<false>, cudaFuncAttributeMaxDynamicSharedMemorySize, SMEM_GEMM);

    k_route<<<1, 256>>>(sel32, out);
    k_convX<<<(T_TOK * D_MODEL / 4) / 256, 256>>>(X);
    dim3 g1(D_FF / 32, D_MODEL / 32, N_EXP);
    k_convWt<<<g1, dim3(32, 8)>>>(W1, 0);
    dim3 g2(D_MODEL / 32, D_FF / 32, N_EXP);
    k_convWt<<<g2, dim3(32, 8)>>>(W2, 1);

    dim3 grid1(MAX_TILES, D_FF / 256);    // 72 x 8 = 576 CTAs
    k_mma<true><<<grid1, 256, SMEM_GEMM>>>(out);
    dim3 grid2(MAX_TILES, D_MODEL / 256); // 72 x 2 = 144 CTAs
    k_mma<false><<<grid2, 256, SMEM_GEMM>>>(out);
}

// round 8
// speedup vs baseline: 4.0528x; 1.1270x over previous
#include <cuda_runtime.h>
#include <cuda_fp16.h>
#include <math.h>
#include <stdint.h>

// Problem constants
#define T_TOK   4096
#define D_MODEL 512
#define D_FF    2048
#define N_EXP   8
#define K_ACT   2
#define NPAIR   (T_TOK * K_ACT)          // 8192
#define BM      128
#define MAX_TILES (NPAIR / BM + N_EXP)   // 72

// ---------------- device scratch ----------------
__device__ int g_pairs[NPAIR];
__device__ int g_tileExpert[MAX_TILES];
__device__ int g_tileRow[MAX_TILES];
__device__ int g_tileRows[MAX_TILES];
__device__ int g_numTiles;

__device__ __align__(16) __half g_Xh [(size_t)T_TOK * D_MODEL];
__device__ __align__(16) __half g_W1t[(size_t)N_EXP * D_FF * D_MODEL]; // [e][n][k]
__device__ __align__(16) __half g_W2t[(size_t)N_EXP * D_MODEL * D_FF]; // [e][d][f]
__device__ __align__(16) __half g_Ht [(size_t)NPAIR * D_FF];           // gelu(X@W1)

// ---------------- PTX helpers (baseline sm_80+) ----------------
__device__ __forceinline__ uint32_t smem_u32(const void* p) {
    uint32_t a;
    asm("{ .reg .u64 t; cvta.to.shared.u64 t, %1; cvt.u32.u64 %0, t; }" : "=r"(a) : "l"(p));
    return a;
}
#define CP16(dst, src)  asm volatile("cp.async.cg.shared.global [%0], [%1], 16;" :: "r"(dst), "l"(src))
#define CP_COMMIT()     asm volatile("cp.async.commit_group;" ::: "memory")
#define CP_WAIT(n)      asm volatile("cp.async.wait_group %0;" :: "n"(n) : "memory")

__device__ __forceinline__ void ldsm_x4(uint32_t* r, uint32_t addr) {
    asm volatile("ldmatrix.sync.aligned.m8n8.x4.shared.b16 {%0,%1,%2,%3}, [%4];"
        : "=r"(r[0]), "=r"(r[1]), "=r"(r[2]), "=r"(r[3]) : "r"(addr));
}
__device__ __forceinline__ void mma16816(float* c, const uint32_t* a, uint32_t b0, uint32_t b1) {
    asm volatile("mma.sync.aligned.m16n8k16.row.col.f32.f16.f16.f32 "
        "{%0,%1,%2,%3}, {%4,%5,%6,%7}, {%8,%9}, {%0,%1,%2,%3};"
        : "+f"(c[0]), "+f"(c[1]), "+f"(c[2]), "+f"(c[3])
        : "r"(a[0]), "r"(a[1]), "r"(a[2]), "r"(a[3]), "r"(b0), "r"(b1));
}

// ---------------- fused routing: init+detect+hist+scan+scatter, 1 block ----
__global__ void k_route(const int* __restrict__ sel32, float* __restrict__ out) {
    __shared__ int sh_cnt[N_EXP];
    __shared__ int sh_off[N_EXP];
    int t = threadIdx.x;  // 256
    if (t < N_EXP) sh_cnt[t] = 0;
    __syncthreads();
    int any = 0;
    for (int i = t; i < NPAIR / 2; i += 256) any |= sel32[2 * i + 1];
    int is32 = __syncthreads_or(any);
    for (int p = t; p < NPAIR; p += 256) {
        int e = is32 ? sel32[p] : sel32[2 * p];
        e = min(max(e, 0), N_EXP - 1);
        atomicAdd(&sh_cnt[e], 1);
    }
    __syncthreads();
    if (t == 0) {
        int off = 0, nt = 0;
        for (int e = 0; e < N_EXP; e++) {
            sh_off[e] = off;
            int c = sh_cnt[e];
            out[(size_t)NPAIR * D_MODEL + e] = (float)c / (float)T_TOK;
            for (int r0 = 0; r0 < c; r0 += BM) {
                g_tileExpert[nt] = e; g_tileRow[nt] = off + r0;
                g_tileRows[nt] = min(BM, c - r0); nt++;
            }
            off += c;
        }
        g_numTiles = nt;
    }
    __syncthreads();
    if (t < N_EXP) sh_cnt[t] = 0;  // reuse as fill counters
    __syncthreads();
    for (int p = t; p < NPAIR; p += 256) {
        int e = is32 ? sel32[p] : sel32[2 * p];
        e = min(max(e, 0), N_EXP - 1);
        int pos = sh_off[e] + atomicAdd(&sh_cnt[e], 1);
        g_pairs[pos] = p;  // intra-expert order never changes output bits
    }
}

// ---------------- conversions ----------------
__global__ void k_convX(const float* __restrict__ X) {
    int i = (blockIdx.x * 256 + threadIdx.x) * 4;
    float4 v = *(const float4*)(X + i);
    __half h[4];
    h[0] = __float2half_rn(v.x); h[1] = __float2half_rn(v.y);
    h[2] = __float2half_rn(v.z); h[3] = __float2half_rn(v.w);
    *(uint2*)(g_Xh + i) = *(uint2*)h;
}

// transpose [R,C] fp32 -> [C,R] fp16, per expert (blockIdx.z)
__global__ void k_convWt(const float* __restrict__ Win, int isW2) {
    const int R = isW2 ? D_FF : D_MODEL;
    const int C = isW2 ? D_MODEL : D_FF;
    int e = blockIdx.z;
    const float* in = Win + (size_t)e * R * C;
    __half* oh = (isW2 ? g_W2t : g_W1t) + (size_t)e * R * C;
    __shared__ float tile[32][33];
    int c0 = blockIdx.x * 32, r0 = blockIdx.y * 32;
    int tx = threadIdx.x, ty = threadIdx.y; // (32, 8)
#pragma unroll
    for (int j = 0; j < 4; j++)
        tile[ty * 4 + j][tx] = in[(size_t)(r0 + ty * 4 + j) * C + c0 + tx];
    __syncthreads();
#pragma unroll
    for (int j = 0; j < 4; j++)
        oh[(size_t)(c0 + ty * 4 + j) * R + r0 + tx] = __float2half_rn(tile[tx][ty * 4 + j]);
}

__device__ __forceinline__ float gelu_exact(float v) {
    return 0.5f * v * (1.0f + erff(v * 0.70710678118654752f));
}

// ---------------- 1-term fp16 GEMM via mma.sync ----------------
// CTA tile 128(M) x 256(N), BK=64, 3-stage cp.async pipeline.
// 512 threads, 16 warps: 4M x 4N grid, warp tile 32(M) x 64(N).
// G1: Ht = gelu(Xh @ W1t^T);  G2: out = Ht @ W2t^T (pair-scattered rows)
#define ROWB   144
#define ARR_A  (128 * ROWB)            // 18432 B
#define ARR_B  (256 * ROWB)            // 36864 B
#define STG    (ARR_A + ARR_B)         // 55296 B
#define NSTG   3
#define SMEM_GEMM (NSTG * STG)         // 165888 B

template<bool G1>
__global__ __launch_bounds__(512, 1) void k_mma(float* __restrict__ out) {
    constexpr int KDIM = G1 ? D_MODEL : D_FF;
    constexpr int NCH  = KDIM / 64;

    int tile = blockIdx.x;
    if (tile >= g_numTiles) return;
    int e    = g_tileExpert[tile];
    int row0 = g_tileRow[tile];
    int rows = g_tileRows[tile];
    int n0   = blockIdx.y * 256;

    extern __shared__ __align__(128) char smem[];
    uint32_t sb = smem_u32(smem);
    __shared__ int s_rows[128];
    __shared__ int s_pair[128];

    int tid = threadIdx.x;
    int wid = tid >> 5, l = tid & 31;

    if (tid < 128) {
        int rr = min(tid, rows - 1);
        int p = g_pairs[row0 + rr];
        s_pair[tid] = p;
        s_rows[tid] = G1 ? (p >> 1) : (row0 + rr);
    }
    __syncthreads();

    const size_t wstride = (size_t)D_FF * D_MODEL;
    const __half* Bw = (G1 ? g_W1t : g_W2t) + (size_t)e * wstride;
    const __half* Asrc = G1 ? g_Xh : g_Ht;

    // per-thread load slices (512 threads)
    // A: 128 rows x 128B; row = tid>>2, quarter 32B (2 CP16)
    int ar = tid >> 2, aq = tid & 3;
    const __half* aP = Asrc + (size_t)s_rows[ar] * KDIM + aq * 16;
    uint32_t dOffA = (uint32_t)ar * ROWB + (uint32_t)aq * 32;
    // B: 256 rows x 128B; row = tid>>1, half 64B (4 CP16)
    int br = tid >> 1, bh = tid & 1;
    const __half* bWp = Bw + (size_t)(n0 + br) * KDIM + bh * 32;
    uint32_t dOffB = (uint32_t)ARR_A + (uint32_t)br * ROWB + (uint32_t)bh * 64;

#define LOAD_STAGE(sidx, k0)                                     \
    {                                                            \
        uint32_t _s = sb + (uint32_t)(sidx) * STG;               \
        _Pragma("unroll")                                        \
        for (int i = 0; i < 2; i++)                              \
            CP16(_s + dOffA + i * 16, aP + (k0) + i * 8);        \
        _Pragma("unroll")                                        \
        for (int i = 0; i < 4; i++)                              \
            CP16(_s + dOffB + i * 16, bWp + (k0) + i * 8);       \
        CP_COMMIT();                                             \
    }

    int warp_m = (wid >> 2) * 32;     // 0,32,64,96
    int warp_n = (wid & 3) * 64;      // 0,64,128,192

    float acc[2][8][4];
#pragma unroll
    for (int i = 0; i < 2; i++)
#pragma unroll
        for (int j = 0; j < 8; j++)
#pragma unroll
            for (int q = 0; q < 4; q++) acc[i][j][q] = 0.0f;

    uint32_t aLane = (uint32_t)((warp_m + (l & 15)) * ROWB + (l >> 4) * 16);
    uint32_t bLane = (uint32_t)ARR_A + (uint32_t)((warp_n + (l & 15)) * ROWB + (l >> 4) * 16);

    LOAD_STAGE(0, 0);
    LOAD_STAGE(1, 64);

    int s = 0;
    for (int c = 0; c < NCH; c++) {
        if (c + 2 < NCH) {
            int sn = s + 2; if (sn >= NSTG) sn -= NSTG;
            LOAD_STAGE(sn, (c + 2) * 64);
        }
        if (c <= NCH - 3)      CP_WAIT(2);
        else if (c == NCH - 2) CP_WAIT(1);
        else                   CP_WAIT(0);
        __syncthreads();
        uint32_t st = sb + (uint32_t)s * STG;
#pragma unroll
        for (int kk = 0; kk < 4; kk++) {
            uint32_t ah[2][4], bw[4][4];
#pragma unroll
            for (int mb = 0; mb < 2; mb++)
                ldsm_x4(ah[mb], st + aLane + (uint32_t)(mb * 16 * ROWB + kk * 32));
#pragma unroll
            for (int nb2 = 0; nb2 < 4; nb2++)
                ldsm_x4(bw[nb2], st + bLane + (uint32_t)(nb2 * 16 * ROWB + kk * 32));
#pragma unroll
            for (int mb = 0; mb < 2; mb++)
#pragma unroll
                for (int nb = 0; nb < 8; nb++) {
                    int nb2 = nb >> 1, sel = nb & 1;
                    mma16816(acc[mb][nb], ah[mb], bw[nb2][sel], bw[nb2][sel + 2]);
                }
        }
        __syncthreads();
        s++; if (s >= NSTG) s = 0;
    }

    // epilogue
#pragma unroll
    for (int mb = 0; mb < 2; mb++)
#pragma unroll
        for (int nb = 0; nb < 8; nb++) {
            int rbase = warp_m + mb * 16 + (l >> 2);
            int col   = warp_n + nb * 8 + (l & 3) * 2;
#pragma unroll
            for (int p = 0; p < 2; p++) {
                int m = rbase + p * 8;
                if (m < rows) {
                    float y0 = acc[mb][nb][2 * p];
                    float y1 = acc[mb][nb][2 * p + 1];
                    if (G1) {
                        __half2 hh;
                        hh.x = __float2half_rn(gelu_exact(y0));
                        hh.y = __float2half_rn(gelu_exact(y1));
                        size_t o = (size_t)(row0 + m) * D_FF + n0 + col;
                        *(uint32_t*)(g_Ht + o) = *(uint32_t*)&hh;
                    } else {
                        size_t o = (size_t)s_pair[m] * D_MODEL + n0 + col;
                        float2 v; v.x = y0; v.y = y1;
                        *(float2*)(out + o) = v;
                    }
                }
            }
        }
#undef LOAD_STAGE
}

// ---------------- launch ----------------
extern "C" void kernel_launch(void* const* d_in, const int* in_sizes, int n_in,
                              void* d_out, int out_size) {
    const float* X     = (const float*)d_in[0];
    const int*   sel32 = (const int*)d_in[1];
    const float* W1    = (const float*)d_in[3];
    const float* W2    = (const float*)d_in[4];
    float*       out   = (float*)d_out;

    cudaFuncSetAttribute((const void*)k_mma<true>,  cudaFuncAttributeMaxDynamicSharedMemorySize, SMEM_GEMM);
    cudaFuncSetAttribute((const void*)k_mma<false>, cudaFuncAttributeMaxDynamicSharedMemorySize, SMEM_GEMM);

    k_route<<<1, 256>>>(sel32, out);
    k_convX<<<(T_TOK * D_MODEL / 4) / 256, 256>>>(X);
    dim3 g1(D_FF / 32, D_MODEL / 32, N_EXP);
    k_convWt<<<g1, dim3(32, 8)>>>(W1, 0);
    dim3 g2(D_MODEL / 32, D_FF / 32, N_EXP);
    k_convWt<<<g2, dim3(32, 8)>>>(W2, 1);

    dim3 grid1(MAX_TILES, D_FF / 256);    // 72 x 8 = 576 CTAs
    k_mma<true><<<grid1, 512, SMEM_GEMM>>>(out);
    dim3 grid2(MAX_TILES, D_MODEL / 256); // 72 x 2 = 144 CTAs
    k_mma<false><<<grid2, 512, SMEM_GEMM>>>(out);
}